// round 7
// baseline (speedup 1.0000x reference)
#include <cuda_runtime.h>

// SequentialLoraA: y_large[b, r] = sum_d x[b,d] * A_large[wids_large[b], d, r]   (r<64)
//                  y_small[b, r] = sum_d x[256+b,d] * A_small[wids_small[b], d, r] (r<16)
//
// Harness carries all f16 tensors as FLOAT32. Output f32: y_large (256*64)
// then y_small (256*16).
//
// Work decomposition: one CTA per (sample, 16-column chunk) = uniform 256 KB
// of adapter streaming per CTA. Large samples -> 4 chunks, small -> 1.
// Grid = 256*4 + 256 = 1280 CTAs. No atomics; each CTA owns 16 outputs.

#define D_DIM    4096
#define B_LARGE  256
#define B_SMALL  256
#define R_LARGE  64
#define R_SMALL  16
#define N_LARGE_CHUNKS (B_LARGE * 4)   // 1024

__global__ __launch_bounds__(256, 6)
void lora_chunk_kernel(const float* __restrict__ x,
                       const int*   __restrict__ wids_large,
                       const int*   __restrict__ wids_small,
                       const float* __restrict__ A_large,
                       const float* __restrict__ A_small,
                       float*       __restrict__ out)
{
    __shared__ float sx[D_DIM];        // 16 KB: this sample's x row
    __shared__ float wsum[8][16];      // per-warp partials for the 16 columns

    const int c    = blockIdx.x;       // 0..1279
    const int tid  = threadIdx.x;      // 0..255
    const int warp = tid >> 5;         // 0..7
    const int lane = tid & 31;

    int          b;        // sample index into x (0..511)
    const float* A;        // base of this chunk's 16 columns
    int          stride;   // floats per adapter row (64 or 16)
    float*       outp;     // where this chunk's 16 outputs go

    if (c < N_LARGE_CHUNKS) {
        b = c >> 2;
        const int rc = (c & 3) * 16;
        A      = A_large + (size_t)wids_large[b] * D_DIM * R_LARGE + rc;
        stride = R_LARGE;
        outp   = out + b * R_LARGE + rc;
    } else {
        const int bs = c - N_LARGE_CHUNKS;
        b      = B_LARGE + bs;
        A      = A_small + (size_t)wids_small[bs] * D_DIM * R_SMALL;
        stride = R_SMALL;
        outp   = out + B_LARGE * R_LARGE + bs * R_SMALL;
    }

    // ---- stage x[b] into shared memory (1024 float4 loads) ----
    const float4* xv  = (const float4*)(x + (size_t)b * D_DIM);
    float4*       sxv = (float4*)sx;
    #pragma unroll
    for (int i = 0; i < 4; ++i) sxv[tid + 256 * i] = xv[tid + 256 * i];
    __syncthreads();

    // Each warp owns 512 d-rows; per iter a warp covers 8 rows x 64 B.
    // lane&3 -> which float4 of the 16-col chunk; lane>>2 -> row within group.
    const int col   = (lane & 3) * 4;
    const int dbase = warp * 512 + (lane >> 2);

    float a0 = 0.f, a1 = 0.f, a2 = 0.f, a3 = 0.f;

    #pragma unroll 4
    for (int it = 0; it < 64; ++it) {
        const int d = dbase + it * 8;
        const float4 v = *(const float4*)(A + (size_t)d * stride + col);
        const float xs = sx[d];
        a0 = fmaf(xs, v.x, a0);
        a1 = fmaf(xs, v.y, a1);
        a2 = fmaf(xs, v.z, a2);
        a3 = fmaf(xs, v.w, a3);
    }

    // reduce over the 8 row-groups (lane bits 2..4)
    #pragma unroll
    for (int m = 4; m <= 16; m <<= 1) {
        a0 += __shfl_xor_sync(0xffffffffu, a0, m);
        a1 += __shfl_xor_sync(0xffffffffu, a1, m);
        a2 += __shfl_xor_sync(0xffffffffu, a2, m);
        a3 += __shfl_xor_sync(0xffffffffu, a3, m);
    }
    if (lane < 4) {
        wsum[warp][col + 0] = a0;
        wsum[warp][col + 1] = a1;
        wsum[warp][col + 2] = a2;
        wsum[warp][col + 3] = a3;
    }
    __syncthreads();

    if (tid < 16) {
        float s = 0.f;
        #pragma unroll
        for (int w = 0; w < 8; ++w) s += wsum[w][tid];
        outp[tid] = s;
    }
}

extern "C" void kernel_launch(void* const* d_in, const int* in_sizes, int n_in,
                              void* d_out, int out_size)
{
    const float* x      = nullptr;
    const float* Alarge = nullptr;
    const float* Asmall = nullptr;
    const int*   widl   = nullptr;
    const int*   widsm  = nullptr;

    for (int i = 0; i < n_in; ++i) {
        const int sz = in_sizes[i];
        if (sz == 512 * D_DIM) {
            x = (const float*)d_in[i];
        } else if (sz == 128 * D_DIM * R_LARGE) {
            Alarge = (const float*)d_in[i];
        } else if (sz == 128 * D_DIM * R_SMALL) {
            Asmall = (const float*)d_in[i];
        } else if (sz == 256) {
            if (!widl) widl = (const int*)d_in[i];
            else       widsm = (const int*)d_in[i];
        }
    }

    float* out = (float*)d_out;
    lora_chunk_kernel<<<N_LARGE_CHUNKS + B_SMALL, 256>>>(
        x, widl, widsm, Alarge, Asmall, out);
}

// round 8
// speedup vs baseline: 1.0430x; 1.0430x over previous
#include <cuda_runtime.h>

// SequentialLoraA, adapter-major formulation.
//   y_large[b,r] = sum_d x[b,d]     * A_large[wids_large[b], d, r]   (r<64)
//   y_small[b,r] = sum_d x[256+b,d] * A_small[wids_small[b], d, r]   (r<16)
// All f16 tensors arrive as FLOAT32. Output f32: y_large (256*64) then
// y_small (256*16).
//
// Kernel 1 buckets samples by adapter id. Kernel 2: one CTA per
// (adapter, 16-column chunk); streams the 256KB adapter chunk from DRAM
// exactly once, multiplying each register-held float4 into accumulators for
// every sample using that adapter (x staged in smem, d-tiled). Unused
// adapters are skipped entirely.

#define D_DIM    4096
#define B_LARGE  256
#define B_SMALL  256
#define R_LARGE  64
#define R_SMALL  16
#define N_ADAPT  128
#define GROUP    8          // samples processed per streaming pass

__device__ int g_cnt_l[N_ADAPT];
__device__ int g_cnt_s[N_ADAPT];
__device__ int g_list_l[N_ADAPT][B_LARGE];
__device__ int g_list_s[N_ADAPT][B_SMALL];

__global__ void prep_kernel(const int* __restrict__ wl,
                            const int* __restrict__ ws)
{
    const int t = threadIdx.x;      // 256 threads
    if (t < N_ADAPT) { g_cnt_l[t] = 0; g_cnt_s[t] = 0; }
    __syncthreads();
    {
        const int w = wl[t];
        const int p = atomicAdd(&g_cnt_l[w], 1);
        g_list_l[w][p] = t;
    }
    {
        const int w = ws[t];
        const int p = atomicAdd(&g_cnt_s[w], 1);
        g_list_s[w][p] = t;
    }
}

__global__ __launch_bounds__(256, 4)
void lora_adapter_kernel(const float* __restrict__ x,
                         const float* __restrict__ A_large,
                         const float* __restrict__ A_small,
                         float*       __restrict__ out)
{
    __shared__ float sxs[GROUP][1024];     // 32 KB: x d-tiles for the group
    __shared__ float wsum[8][GROUP][16];   // 4 KB: per-warp partials

    const int c    = blockIdx.x;           // 0..639
    const int tid  = threadIdx.x;
    const int warp = tid >> 5;
    const int lane = tid & 31;

    const bool is_large = (c < N_ADAPT * 4);
    int w, rc, cnt, stride;
    const int*   list;
    const float* A;

    if (is_large) {
        w      = c >> 2;
        rc     = (c & 3) * 16;
        cnt    = g_cnt_l[w];
        list   = g_list_l[w];
        A      = A_large + (size_t)w * D_DIM * R_LARGE + rc;
        stride = R_LARGE;
    } else {
        w      = c - N_ADAPT * 4;
        rc     = 0;
        cnt    = g_cnt_s[w];
        list   = g_list_s[w];
        A      = A_small + (size_t)w * D_DIM * R_SMALL;
        stride = R_SMALL;
    }
    if (cnt == 0) return;                  // unused adapter: no traffic

    const int col    = (lane & 3) * 4;     // which float4 of the 16 columns
    const int rowsub = lane >> 2;          // 0..7: row within 8-row group
    const int dbase  = warp * 128 + rowsub;

    for (int g = 0; g < cnt; g += GROUP) {
        const int gcnt = min(GROUP, cnt - g);

        float4 acc[GROUP];
        #pragma unroll
        for (int s = 0; s < GROUP; ++s) acc[s] = make_float4(0.f, 0.f, 0.f, 0.f);

        for (int t = 0; t < 4; ++t) {      // d-tiles of 1024
            __syncthreads();               // previous tile fully consumed
            for (int i = tid; i < gcnt * 256; i += 256) {
                const int s  = i >> 8;     // sample slot
                const int j  = i & 255;    // float4 within tile
                const int b  = list[g + s];
                const int xb = is_large ? b : (B_LARGE + b);
                ((float4*)sxs[s])[j] =
                    ((const float4*)(x + (size_t)xb * D_DIM + t * 1024))[j];
            }
            __syncthreads();

            const float* At = A + (size_t)t * 1024 * stride;
            #pragma unroll 4
            for (int it = 0; it < 16; ++it) {
                const int d = dbase + it * 8;
                const float4 v = *(const float4*)(At + (size_t)d * stride + col);
                #pragma unroll
                for (int s = 0; s < GROUP; ++s) {
                    if (s < gcnt) {
                        const float xs = sxs[s][d];
                        acc[s].x = fmaf(xs, v.x, acc[s].x);
                        acc[s].y = fmaf(xs, v.y, acc[s].y);
                        acc[s].z = fmaf(xs, v.z, acc[s].z);
                        acc[s].w = fmaf(xs, v.w, acc[s].w);
                    }
                }
            }
        }

        // reduce over the 8 row-groups (lane bits 2..4)
        #pragma unroll
        for (int s = 0; s < GROUP; ++s) {
            if (s < gcnt) {
                #pragma unroll
                for (int m = 4; m <= 16; m <<= 1) {
                    acc[s].x += __shfl_xor_sync(0xffffffffu, acc[s].x, m);
                    acc[s].y += __shfl_xor_sync(0xffffffffu, acc[s].y, m);
                    acc[s].z += __shfl_xor_sync(0xffffffffu, acc[s].z, m);
                    acc[s].w += __shfl_xor_sync(0xffffffffu, acc[s].w, m);
                }
            }
        }
        __syncthreads();
        if (lane < 4) {
            #pragma unroll
            for (int s = 0; s < GROUP; ++s) {
                if (s < gcnt) {
                    wsum[warp][s][col + 0] = acc[s].x;
                    wsum[warp][s][col + 1] = acc[s].y;
                    wsum[warp][s][col + 2] = acc[s].z;
                    wsum[warp][s][col + 3] = acc[s].w;
                }
            }
        }
        __syncthreads();

        if (tid < gcnt * 16) {
            const int s = tid >> 4;
            const int r = tid & 15;
            float sum = 0.f;
            #pragma unroll
            for (int ww = 0; ww < 8; ++ww) sum += wsum[ww][s][r];
            const int b = list[g + s];
            if (is_large) out[b * R_LARGE + rc + r] = sum;
            else          out[B_LARGE * R_LARGE + b * R_SMALL + r] = sum;
        }
    }
}

extern "C" void kernel_launch(void* const* d_in, const int* in_sizes, int n_in,
                              void* d_out, int out_size)
{
    const float* x      = nullptr;
    const float* Alarge = nullptr;
    const float* Asmall = nullptr;
    const int*   widl   = nullptr;
    const int*   widsm  = nullptr;

    for (int i = 0; i < n_in; ++i) {
        const int sz = in_sizes[i];
        if (sz == 512 * D_DIM) {
            x = (const float*)d_in[i];
        } else if (sz == 128 * D_DIM * R_LARGE) {
            Alarge = (const float*)d_in[i];
        } else if (sz == 128 * D_DIM * R_SMALL) {
            Asmall = (const float*)d_in[i];
        } else if (sz == 256) {
            if (!widl) widl = (const int*)d_in[i];
            else       widsm = (const int*)d_in[i];
        }
    }

    float* out = (float*)d_out;
    prep_kernel<<<1, 256>>>(widl, widsm);
    lora_adapter_kernel<<<N_ADAPT * 4 + N_ADAPT, 256>>>(x, Alarge, Asmall, out);
}